// round 1
// baseline (speedup 1.0000x reference)
#include <cuda_runtime.h>
#include <cstdint>

// ---------------------------------------------------------------------------
// ValueNetwork forward. Dead-code-eliminated: mlp1/global/attn branch unused.
// Live graph: self6 = state[:,0,:6]; LSTM(64 steps, in=7, hid=50) over
// state[:,:,6:13]; MLP 56->150->100->100->1.
// ---------------------------------------------------------------------------

#define B_SIZE 8192
#define NSTEP  64
#define DDIM   13
#define HID    50
#define KDIM   57          // 7 input + 50 hidden
#define GATE   200
#define GPAD   224         // 32 lanes * 7 cols
#define RPB    64          // batch rows per block
#define THREADS 256
#define RSTR   66          // padded row stride (even, !=64) for transposed smem

// scratch (static device arrays: allocation-free)
__device__ float g_xT[NSTEP * 7 * B_SIZE];     // [t][k][b]
__device__ float g_jointT[56 * B_SIZE];        // [k][b]: rows 0-5 self, 6-55 h_n

// ---- f32x2 helpers (sm_103a packed fp32 FMA: 2x FFMA throughput) ----------
__device__ __forceinline__ unsigned long long dup2(float v) {
    unsigned long long r;
    asm("mov.b64 %0, {%1, %1};" : "=l"(r) : "f"(v));
    return r;
}
__device__ __forceinline__ void fma2(unsigned long long& d,
                                     unsigned long long a,
                                     unsigned long long b) {
    asm("fma.rn.f32x2 %0, %1, %2, %0;" : "+l"(d) : "l"(a), "l"(b));
}
__device__ __forceinline__ float2 unpk(unsigned long long v) {
    float2 f;
    asm("mov.b64 {%0, %1}, %2;" : "=f"(f.x), "=f"(f.y) : "l"(v));
    return f;
}

__device__ __forceinline__ float sig_f(float x) {
    return __fdividef(1.f, 1.f + __expf(-x));
}
__device__ __forceinline__ float tanh_f(float x) {
    float xc = fminf(fmaxf(x, -15.f), 15.f);   // avoid exp overflow -> nan
    float e = __expf(2.f * xc);
    return __fdividef(e - 1.f, e + 1.f);
}

// ---------------------------------------------------------------------------
// prep: state (B,64,13) -> xT[t][k][b] (time-major, coalesced) + self6 -> jointT
// ---------------------------------------------------------------------------
#define PREP_BT 16
__global__ __launch_bounds__(THREADS) void prep_kernel(const float* __restrict__ state) {
    __shared__ float sh[PREP_BT][449];          // 449: odd stride, conflict-free
    const int b0 = blockIdx.x * PREP_BT;
    // coalesced read of 16 full batch rows (16*64*13 floats)
    for (int idx = threadIdx.x; idx < PREP_BT * NSTEP * DDIM; idx += THREADS) {
        int bb = idx / (NSTEP * DDIM);
        int rem = idx - bb * (NSTEP * DDIM);
        int t = rem / DDIM;
        int d = rem - t * DDIM;
        float v = state[(size_t)b0 * (NSTEP * DDIM) + idx];
        if (d >= 6)       sh[bb][t * 7 + (d - 6)] = v;
        else if (t == 0)  g_jointT[d * B_SIZE + b0 + bb] = v;
    }
    __syncthreads();
    // coalesced write of xT
    for (int idx = threadIdx.x; idx < PREP_BT * NSTEP * 7; idx += THREADS) {
        int bb = idx & (PREP_BT - 1);
        int tk = idx >> 4;
        g_xT[(size_t)tk * B_SIZE + b0 + bb] = sh[bb][tk];
    }
}

// ---------------------------------------------------------------------------
// LSTM: 128 blocks x 64 rows, persistent over 64 steps.
// smem: W[57][224] | bias[224] | hx[57][66] (transposed, rows 0-6 = x, 7-56 = h)
//       | c[50][66] | gates[200][66]
// ---------------------------------------------------------------------------
#define LSTM_SM_FLOATS (KDIM*GPAD + GPAD + KDIM*RSTR + HID*RSTR + GATE*RSTR)
#define LSTM_SM_BYTES  (LSTM_SM_FLOATS * 4)

__global__ __launch_bounds__(THREADS) void lstm_kernel(
    const float* __restrict__ wih, const float* __restrict__ whh,
    const float* __restrict__ bih, const float* __restrict__ bhh)
{
    extern __shared__ float sm[];
    float* Wsh  = sm;                       // 57*224
    float* bsh  = Wsh + KDIM * GPAD;        // 224
    float* hxsh = bsh + GPAD;               // 57*66
    float* csh  = hxsh + KDIM * RSTR;       // 50*66
    float* gsh  = csh + HID * RSTR;         // 200*66

    const int tid = threadIdx.x;
    const int b0  = blockIdx.x * RPB;

    for (int idx = tid; idx < KDIM * GPAD; idx += THREADS) {
        int k = idx / GPAD, c = idx - k * GPAD;
        Wsh[idx] = (c < GATE) ? (k < 7 ? wih[k * GATE + c] : whh[(k - 7) * GATE + c]) : 0.f;
    }
    for (int idx = tid; idx < GPAD; idx += THREADS)
        bsh[idx] = (idx < GATE) ? bih[idx] + bhh[idx] : 0.f;
    for (int idx = tid; idx < KDIM * RSTR; idx += THREADS) hxsh[idx] = 0.f;
    for (int idx = tid; idx < HID * RSTR; idx += THREADS)  csh[idx]  = 0.f;
    __syncthreads();

    const int lane = tid & 31;
    const int rb   = (tid >> 5) * 8;    // 8 warps * 8 rows = 64 rows

    for (int t = 0; t < NSTEP; ++t) {
        // stage x(t) into hx rows 0..6 (coalesced from xT)
        for (int idx = tid; idx < 7 * RPB; idx += THREADS) {
            int k = idx >> 6, r = idx & 63;
            hxsh[k * RSTR + r] = g_xT[(t * 7 + k) * B_SIZE + b0 + r];
        }
        __syncthreads();

        // gates[64][224] = hx[64][57] @ W[57][224] + bias, f32x2 row-paired
        unsigned long long acc[4][7];
        #pragma unroll
        for (int j = 0; j < 7; ++j) {
            unsigned long long bv = dup2(bsh[lane * 7 + j]);
            acc[0][j] = bv; acc[1][j] = bv; acc[2][j] = bv; acc[3][j] = bv;
        }
        #pragma unroll 3
        for (int k = 0; k < KDIM; ++k) {
            const float* hr = &hxsh[k * RSTR + rb];
            unsigned long long h0 = *(const unsigned long long*)(hr);
            unsigned long long h1 = *(const unsigned long long*)(hr + 2);
            unsigned long long h2 = *(const unsigned long long*)(hr + 4);
            unsigned long long h3 = *(const unsigned long long*)(hr + 6);
            const float* wr = &Wsh[k * GPAD + lane * 7];
            #pragma unroll
            for (int j = 0; j < 7; ++j) {
                unsigned long long w2 = dup2(wr[j]);
                fma2(acc[0][j], h0, w2);
                fma2(acc[1][j], h1, w2);
                fma2(acc[2][j], h2, w2);
                fma2(acc[3][j], h3, w2);
            }
        }
        #pragma unroll
        for (int j = 0; j < 7; ++j) {
            int c = lane * 7 + j;
            if (c < GATE) {
                float* gp = &gsh[c * RSTR + rb];
                *(unsigned long long*)(gp)     = acc[0][j];
                *(unsigned long long*)(gp + 2) = acc[1][j];
                *(unsigned long long*)(gp + 4) = acc[2][j];
                *(unsigned long long*)(gp + 6) = acc[3][j];
            }
        }
        __syncthreads();

        // activation / state update (i,f,g,o regroup via gsh)
        for (int idx = tid; idx < HID * RPB; idx += THREADS) {
            int r = idx & 63, u = idx >> 6;
            float gi = gsh[u * RSTR + r];
            float gf = gsh[(HID + u) * RSTR + r];
            float gg = gsh[(2 * HID + u) * RSTR + r];
            float go = gsh[(3 * HID + u) * RSTR + r];
            float c  = csh[u * RSTR + r];
            c = sig_f(gf) * c + sig_f(gi) * tanh_f(gg);
            csh[u * RSTR + r] = c;
            hxsh[(7 + u) * RSTR + r] = sig_f(go) * tanh_f(c);
        }
        // (next iter's top __syncthreads orders h-writes before next GEMM)
    }
    __syncthreads();
    for (int idx = tid; idx < HID * RPB; idx += THREADS) {
        int r = idx & 63, u = idx >> 6;
        g_jointT[(6 + u) * B_SIZE + b0 + r] = hxsh[(7 + u) * RSTR + r];
    }
}

// ---------------------------------------------------------------------------
// MLP: all weights in smem, transposed activation buffers, f32x2 GEMMs.
// ---------------------------------------------------------------------------
template<int IN, int OUT, int LA, int CP>
__device__ __forceinline__ void mlp_layer(const float* __restrict__ Wsh,
                                          const float* __restrict__ Bsh,
                                          const float* __restrict__ Xsh,
                                          float* __restrict__ Ysh,
                                          int lane, int rb)
{
    unsigned long long acc[4][CP];
    const bool act = lane < LA;
    #pragma unroll
    for (int j = 0; j < CP; ++j) {
        unsigned long long bv = dup2(act ? Bsh[j * LA + lane] : 0.f);
        acc[0][j] = bv; acc[1][j] = bv; acc[2][j] = bv; acc[3][j] = bv;
    }
    #pragma unroll 2
    for (int k = 0; k < IN; ++k) {
        const float* xr = &Xsh[k * RSTR + rb];
        unsigned long long h0 = *(const unsigned long long*)(xr);
        unsigned long long h1 = *(const unsigned long long*)(xr + 2);
        unsigned long long h2 = *(const unsigned long long*)(xr + 4);
        unsigned long long h3 = *(const unsigned long long*)(xr + 6);
        #pragma unroll
        for (int j = 0; j < CP; ++j) {
            unsigned long long w2 = dup2(act ? Wsh[k * OUT + j * LA + lane] : 0.f);
            fma2(acc[0][j], h0, w2);
            fma2(acc[1][j], h1, w2);
            fma2(acc[2][j], h2, w2);
            fma2(acc[3][j], h3, w2);
        }
    }
    if (act) {
        #pragma unroll
        for (int j = 0; j < CP; ++j) {
            int c = j * LA + lane;
            float* yp = &Ysh[c * RSTR + rb];
            #pragma unroll
            for (int rp = 0; rp < 4; ++rp) {
                float2 v = unpk(acc[rp][j]);
                v.x = fmaxf(v.x, 0.f);
                v.y = fmaxf(v.y, 0.f);
                *(float2*)(yp + 2 * rp) = v;
            }
        }
    }
}

#define MLP_SM_FLOATS (8400 + 150 + 15000 + 100 + 10000 + 100 + 100 + 2 + 150*RSTR + 150*RSTR)
#define MLP_SM_BYTES  (MLP_SM_FLOATS * 4)

__global__ __launch_bounds__(THREADS) void mlp_kernel(
    const float* __restrict__ w1, const float* __restrict__ b1,
    const float* __restrict__ w2, const float* __restrict__ b2,
    const float* __restrict__ w3, const float* __restrict__ b3,
    const float* __restrict__ w4, const float* __restrict__ b4,
    float* __restrict__ out)
{
    extern __shared__ float sm[];
    float* w1s = sm;                // 8400
    float* b1s = w1s + 8400;        // 150
    float* w2s = b1s + 150;         // 15000
    float* b2s = w2s + 15000;       // 100
    float* w3s = b2s + 100;         // 10000
    float* b3s = w3s + 10000;       // 100
    float* w4s = b3s + 100;         // 100
    float* b4s = w4s + 100;         // 1 (+1 pad)
    float* X   = b4s + 2;           // 150*66
    float* Y   = X + 150 * RSTR;    // 150*66

    const int tid = threadIdx.x;
    const int b0  = blockIdx.x * RPB;

    for (int i = tid; i < 8400; i += THREADS)  w1s[i] = w1[i];
    for (int i = tid; i < 15000; i += THREADS) w2s[i] = w2[i];
    for (int i = tid; i < 10000; i += THREADS) w3s[i] = w3[i];
    for (int i = tid; i < 150; i += THREADS)   b1s[i] = b1[i];
    for (int i = tid; i < 100; i += THREADS) {
        b2s[i] = b2[i]; b3s[i] = b3[i]; w4s[i] = w4[i];
    }
    if (tid == 0) b4s[0] = b4[0];
    for (int idx = tid; idx < 56 * RPB; idx += THREADS) {
        int r = idx & 63, k = idx >> 6;
        X[k * RSTR + r] = g_jointT[k * B_SIZE + b0 + r];
    }
    __syncthreads();

    const int lane = tid & 31;
    const int rb   = (tid >> 5) * 8;

    mlp_layer<56, 150, 30, 5>(w1s, b1s, X, Y, lane, rb);
    __syncthreads();
    mlp_layer<150, 100, 25, 4>(w2s, b2s, Y, X, lane, rb);
    __syncthreads();
    mlp_layer<100, 100, 25, 4>(w3s, b3s, X, Y, lane, rb);
    __syncthreads();

    if (tid < RPB) {
        float a0 = 0.f, a1 = 0.f, a2 = 0.f, a3 = 0.f;
        #pragma unroll 5
        for (int k = 0; k < 100; k += 4) {
            a0 += Y[k * RSTR + tid]       * w4s[k];
            a1 += Y[(k + 1) * RSTR + tid] * w4s[k + 1];
            a2 += Y[(k + 2) * RSTR + tid] * w4s[k + 2];
            a3 += Y[(k + 3) * RSTR + tid] * w4s[k + 3];
        }
        out[b0 + tid] = a0 + a1 + a2 + a3 + b4s[0];
    }
}

// ---------------------------------------------------------------------------
extern "C" void kernel_launch(void* const* d_in, const int* in_sizes, int n_in,
                              void* d_out, int out_size)
{
    (void)in_sizes; (void)n_in; (void)out_size;
    const float* state = (const float*)d_in[0];
    const float* wih   = (const float*)d_in[11];
    const float* whh   = (const float*)d_in[12];
    const float* bih   = (const float*)d_in[13];
    const float* bhh   = (const float*)d_in[14];
    const float* w1    = (const float*)d_in[15];
    const float* b1    = (const float*)d_in[16];
    const float* w2    = (const float*)d_in[17];
    const float* b2    = (const float*)d_in[18];
    const float* w3    = (const float*)d_in[19];
    const float* b3    = (const float*)d_in[20];
    const float* w4    = (const float*)d_in[21];
    const float* b4    = (const float*)d_in[22];
    float* out = (float*)d_out;

    cudaFuncSetAttribute(lstm_kernel, cudaFuncAttributeMaxDynamicSharedMemorySize, LSTM_SM_BYTES);
    cudaFuncSetAttribute(mlp_kernel,  cudaFuncAttributeMaxDynamicSharedMemorySize, MLP_SM_BYTES);

    prep_kernel<<<B_SIZE / PREP_BT, THREADS>>>(state);
    lstm_kernel<<<B_SIZE / RPB, THREADS, LSTM_SM_BYTES>>>(wih, whh, bih, bhh);
    mlp_kernel<<<B_SIZE / RPB, THREADS, MLP_SM_BYTES>>>(w1, b1, w2, b2, w3, b3, w4, b4, out);
}